// round 10
// baseline (speedup 1.0000x reference)
#include <cuda_runtime.h>

#define HW   4096
#define NC   128
#define CR   32
#define KK   49

// scratch for generated per-pixel kernels: [B=4][49][64*64]
__device__ float g_kernel[4 * KK * HW];
// prepped weights: w1 transposed [c][o], BN scale/shift
__device__ float g_w1t[NC * CR];
__device__ float g_scale[CR];
__device__ float g_shift[CR];

// ---------------------------------------------------------------------------
// Kernel 0: prep. Transpose w1 -> [c][o]; fold b1/BN into scale/shift.
// ---------------------------------------------------------------------------
__global__ __launch_bounds__(128) void prep_kernel(
    const float* __restrict__ w1, const float* __restrict__ b1,
    const float* __restrict__ gamma, const float* __restrict__ beta,
    const float* __restrict__ mean,  const float* __restrict__ var)
{
    const int tid = threadIdx.x;
    for (int i = tid; i < NC * CR; i += 128) {
        int o = i >> 7, c = i & 127;
        g_w1t[c * CR + o] = w1[i];
    }
    if (tid < CR) {
        float sc = gamma[tid] * rsqrtf(var[tid] + 1e-5f);
        g_scale[tid] = sc;
        g_shift[tid] = fmaf(b1[tid], sc, beta[tid] - mean[tid] * sc);
    }
}

// ---------------------------------------------------------------------------
// Kernel 1: generate involution kernels.
// 512 blocks x 128 threads. Block = 32 pixels, 4 "parts" per pixel.
// Weights read directly from gmem (warp-uniform LDG, L1-resident after
// first touch) -- no per-block smem staging. Only fbuf (16KB) in smem.
// ---------------------------------------------------------------------------
__global__ __launch_bounds__(128, 6) void gen_kernel(
    const float* __restrict__ x, const float* __restrict__ w2,
    const float* __restrict__ b2)
{
    __shared__ __align__(16) float fbuf[4 * CR * 32]; // [part][o][pix] 16 KB

    const int tid   = threadIdx.x;
    const int pix_l = tid & 31;
    const int part  = tid >> 5;            // warp id 0..3
    const int pixel = blockIdx.x * 32 + pix_l;
    const int b     = pixel >> 12;
    const int hw    = pixel & (HW - 1);

    // ---- stage 1: partial 1x1 conv over this part's 32 channels ----
    float fp[CR];
    #pragma unroll
    for (int o = 0; o < CR; o++) fp[o] = 0.f;

    const float* xp = x + ((size_t)(b * NC + part * 32)) * HW + hw;
    #pragma unroll 8
    for (int c = 0; c < 32; c++) {
        float xv = xp[(size_t)c * HW];
        const float4* wr = (const float4*)&g_w1t[(part * 32 + c) * CR];
        #pragma unroll
        for (int o4 = 0; o4 < 8; o4++) {
            float4 w = wr[o4];
            fp[o4*4+0] = fmaf(w.x, xv, fp[o4*4+0]);
            fp[o4*4+1] = fmaf(w.y, xv, fp[o4*4+1]);
            fp[o4*4+2] = fmaf(w.z, xv, fp[o4*4+2]);
            fp[o4*4+3] = fmaf(w.w, xv, fp[o4*4+3]);
        }
    }
    {
        float* fb = fbuf + part * (CR * 32) + pix_l;
        #pragma unroll
        for (int o = 0; o < CR; o++) fb[o * 32] = fp[o];
    }
    __syncthreads();

    // ---- stage 2: combine partials + BN + ReLU ----
    float f[CR];
    #pragma unroll
    for (int o = 0; o < CR; o++) {
        float v = fbuf[0*(CR*32) + o*32 + pix_l]
                + fbuf[1*(CR*32) + o*32 + pix_l]
                + fbuf[2*(CR*32) + o*32 + pix_l]
                + fbuf[3*(CR*32) + o*32 + pix_l];
        v = fmaf(v, g_scale[o], g_shift[o]);
        f[o] = fmaxf(v, 0.f);
    }

    // ---- stage 3: this part's 13 kernel outputs (w2 is already [t][o]) ----
    const int t0 = part * 13;
    float* kp = g_kernel + (size_t)b * KK * HW + hw;
    #pragma unroll
    for (int tt = 0; tt < 13; tt++) {
        int t = t0 + tt;
        if (t < KK) {
            const float4* wr = (const float4*)&w2[t * CR];
            float a0 = 0.f, a1 = 0.f, a2 = 0.f, a3 = 0.f;
            #pragma unroll
            for (int o4 = 0; o4 < 8; o4++) {
                float4 w = wr[o4];
                a0 = fmaf(w.x, f[o4*4+0], a0);
                a1 = fmaf(w.y, f[o4*4+1], a1);
                a2 = fmaf(w.z, f[o4*4+2], a2);
                a3 = fmaf(w.w, f[o4*4+3], a3);
            }
            kp[(size_t)t * HW] = (a0 + a1) + (a2 + a3) + b2[t];
        }
    }
}

// ---------------------------------------------------------------------------
// Kernel 2: involution accumulation (R6 winner, unchanged).
// grid 1024 = (b, 16 4-row tiles, 16 8-channel groups), 128 threads.
// Halo: 10 aligned LDG.128 per thread + small edge-zero pass.
// taps-outer/channels-inner, kv double-buffered, 16 FMA chains.
// ---------------------------------------------------------------------------
__global__ __launch_bounds__(128, 6) void inv_kernel(
    const float* __restrict__ x, float* __restrict__ out)
{
    __shared__ __align__(16) float xs[8 * 10 * 72];   // 23040 B

    const int bx = blockIdx.x;              // 0..1023
    const int b  = bx >> 8;
    const int ht = (bx >> 4) & 15;          // 16 row-tiles of 4
    const int cg = bx & 15;                 // 16 groups of 8 channels
    const int h0 = ht * 4;
    const int c0 = cg * 8;

    const int tid  = threadIdx.x;
    const int hloc = tid >> 5;              // 0..3
    const int lane = tid & 31;
    const int wloc = lane * 2;

    // ---- halo main fill: 1280 aligned float4 loads (10 per thread) ----
    #pragma unroll
    for (int it = 0; it < 10; it++) {
        int idx = tid + it * 128;           // 0..1279
        int ch  = idx / 160;
        int rem = idx - ch * 160;
        int r   = rem >> 4;
        int k   = rem & 15;
        int gr  = h0 - 3 + r;
        float4 v = make_float4(0.f, 0.f, 0.f, 0.f);
        if ((unsigned)gr < 64u)
            v = *(const float4*)(x + ((size_t)(b * NC + c0 + ch) << 12)
                                   + (gr << 6) + (k << 2));
        float* d = xs + ch * 720 + r * 72 + 3 + (k << 2);
        d[0] = v.x; d[1] = v.y; d[2] = v.z; d[3] = v.w;
    }
    // ---- halo edges: cols 0..2 and 67..71 -> zero ----
    #pragma unroll
    for (int it = 0; it < 5; it++) {
        int idx = tid + it * 128;           // 0..639
        int ch  = idx / 80;
        int rem = idx - ch * 80;
        int r   = rem >> 3;
        int e   = rem & 7;
        int col = (e < 3) ? e : (64 + e);   // 0,1,2,67..71
        xs[ch * 720 + r * 72 + col] = 0.f;
    }

    const float* kpix = g_kernel + (size_t)b * KK * HW + (h0 + hloc) * 64 + wloc;

    float ax[8], ay[8];
    #pragma unroll
    for (int cc = 0; cc < 8; cc++) { ax[cc] = 0.f; ay[cc] = 0.f; }

    // prefetch kernel row 0
    float2 kr[7], krn[7];
    #pragma unroll
    for (int j = 0; j < 7; j++)
        kr[j] = *(const float2*)(kpix + (size_t)j * HW);

    __syncthreads();

    #pragma unroll 1
    for (int i = 0; i < 7; i++) {
        if (i < 6) {
            #pragma unroll
            for (int j = 0; j < 7; j++)
                krn[j] = *(const float2*)(kpix + (size_t)((i + 1) * 7 + j) * HW);
        }
        const float* xrow = xs + (hloc + i) * 72 + wloc;
        #pragma unroll
        for (int cc = 0; cc < 8; cc++) {
            const float2* rp = (const float2*)(xrow + cc * 720);
            float2 v0 = rp[0], v1 = rp[1], v2 = rp[2], v3 = rp[3];
            float a = ax[cc], y = ay[cc];
            a = fmaf(kr[0].x, v0.x, a);  y = fmaf(kr[0].y, v0.y, y);
            a = fmaf(kr[1].x, v0.y, a);  y = fmaf(kr[1].y, v1.x, y);
            a = fmaf(kr[2].x, v1.x, a);  y = fmaf(kr[2].y, v1.y, y);
            a = fmaf(kr[3].x, v1.y, a);  y = fmaf(kr[3].y, v2.x, y);
            a = fmaf(kr[4].x, v2.x, a);  y = fmaf(kr[4].y, v2.y, y);
            a = fmaf(kr[5].x, v2.y, a);  y = fmaf(kr[5].y, v3.x, y);
            a = fmaf(kr[6].x, v3.x, a);  y = fmaf(kr[6].y, v3.y, y);
            ax[cc] = a; ay[cc] = y;
        }
        #pragma unroll
        for (int j = 0; j < 7; j++) kr[j] = krn[j];
    }

    const size_t out_pix = (size_t)(h0 + hloc) * 64 + wloc;
    #pragma unroll
    for (int cc = 0; cc < 8; cc++) {
        float2 res; res.x = ax[cc]; res.y = ay[cc];
        *(float2*)(out + ((size_t)(b * NC + c0 + cc) << 12) + out_pix) = res;
    }
}

extern "C" void kernel_launch(void* const* d_in, const int* in_sizes, int n_in,
                              void* d_out, int out_size)
{
    const float* x     = (const float*)d_in[0];
    const float* w1    = (const float*)d_in[1];
    const float* b1    = (const float*)d_in[2];
    const float* gamma = (const float*)d_in[3];
    const float* beta  = (const float*)d_in[4];
    const float* mean  = (const float*)d_in[5];
    const float* var   = (const float*)d_in[6];
    const float* w2    = (const float*)d_in[7];
    const float* b2    = (const float*)d_in[8];

    prep_kernel<<<1, 128>>>(w1, b1, gamma, beta, mean, var);
    gen_kernel<<<512, 128>>>(x, w2, b2);
    inv_kernel<<<1024, 128>>>(x, (float*)d_out);
}

// round 11
// speedup vs baseline: 1.0944x; 1.0944x over previous
#include <cuda_runtime.h>

#define HW   4096
#define NC   128
#define CR   32
#define KK   49

typedef unsigned long long u64t;

__device__ __forceinline__ u64t pack2(float lo, float hi) {
    u64t r; asm("mov.b64 %0,{%1,%2};" : "=l"(r) : "f"(lo), "f"(hi)); return r;
}
__device__ __forceinline__ void unpack2(u64t v, float& lo, float& hi) {
    asm("mov.b64 {%0,%1},%2;" : "=f"(lo), "=f"(hi) : "l"(v));
}
__device__ __forceinline__ u64t ffma2(u64t a, u64t b, u64t c) {
    u64t d; asm("fma.rn.f32x2 %0,%1,%2,%3;" : "=l"(d) : "l"(a), "l"(b), "l"(c));
    return d;
}

// scratch for generated per-pixel kernels: [B=4][49][64*64]
__device__ float g_kernel[4 * KK * HW];

// ---------------------------------------------------------------------------
// Kernel 1: generate involution kernels (R4 proven version).
// 256 blocks x 256 threads. Block = 64 pixels, 4 "parts" per pixel.
// ---------------------------------------------------------------------------
__global__ __launch_bounds__(256, 3) void gen_kernel(
    const float* __restrict__ x,  const float* __restrict__ w1,
    const float* __restrict__ b1, const float* __restrict__ gamma,
    const float* __restrict__ beta, const float* __restrict__ mean,
    const float* __restrict__ var,  const float* __restrict__ w2,
    const float* __restrict__ b2)
{
    __shared__ __align__(16) float w1t[NC * CR];      // [c][o]  16 KB
    __shared__ __align__(16) float w2tt[52 * CR];     // [t][o]  6.5 KB
    __shared__ __align__(16) float fbuf[4 * CR * 64]; // [part][o][pix] 32 KB
    __shared__ float s_scale[CR], s_shift[CR];

    const int tid = threadIdx.x;

    for (int i = tid; i < NC * CR; i += 256) {
        int o = i >> 7, c = i & 127;
        w1t[c * CR + o] = w1[i];
    }
    for (int i = tid; i < 52 * CR; i += 256)
        w2tt[i] = (i < KK * CR) ? w2[i] : 0.f;
    if (tid < CR) {
        float sc = gamma[tid] * rsqrtf(var[tid] + 1e-5f);
        s_scale[tid] = sc;
        s_shift[tid] = fmaf(b1[tid], sc, beta[tid] - mean[tid] * sc);
    }
    __syncthreads();

    const int pix_l = tid & 63;
    const int part  = tid >> 6;            // warp-uniform
    const int pixel = blockIdx.x * 64 + pix_l;
    const int b     = pixel >> 12;
    const int hw    = pixel & (HW - 1);

    // ---- stage 1: partial 1x1 conv over this part's 32 channels ----
    float fp[CR];
    #pragma unroll
    for (int o = 0; o < CR; o++) fp[o] = 0.f;

    const float* xp = x + ((size_t)(b * NC + part * 32)) * HW + hw;
    #pragma unroll 8
    for (int c = 0; c < 32; c++) {
        float xv = xp[(size_t)c * HW];
        const float4* wr = (const float4*)&w1t[(part * 32 + c) * CR];
        #pragma unroll
        for (int o4 = 0; o4 < 8; o4++) {
            float4 w = wr[o4];
            fp[o4*4+0] = fmaf(w.x, xv, fp[o4*4+0]);
            fp[o4*4+1] = fmaf(w.y, xv, fp[o4*4+1]);
            fp[o4*4+2] = fmaf(w.z, xv, fp[o4*4+2]);
            fp[o4*4+3] = fmaf(w.w, xv, fp[o4*4+3]);
        }
    }
    {
        float* fb = fbuf + part * (CR * 64) + pix_l;
        #pragma unroll
        for (int o = 0; o < CR; o++) fb[o * 64] = fp[o];
    }
    __syncthreads();

    // ---- stage 2: combine partials + BN + ReLU ----
    float f[CR];
    #pragma unroll
    for (int o = 0; o < CR; o++) {
        float v = fbuf[0*(CR*64) + o*64 + pix_l]
                + fbuf[1*(CR*64) + o*64 + pix_l]
                + fbuf[2*(CR*64) + o*64 + pix_l]
                + fbuf[3*(CR*64) + o*64 + pix_l];
        v = fmaf(v, s_scale[o], s_shift[o]);
        f[o] = fmaxf(v, 0.f);
    }

    // ---- stage 3: this part's 13 kernel outputs ----
    const int t0 = part * 13;
    float* kp = g_kernel + (size_t)b * KK * HW + hw;
    #pragma unroll
    for (int tt = 0; tt < 13; tt++) {
        int t = t0 + tt;
        const float4* wr = (const float4*)&w2tt[t * CR];
        float a0 = 0.f, a1 = 0.f, a2 = 0.f, a3 = 0.f;
        #pragma unroll
        for (int o4 = 0; o4 < 8; o4++) {
            float4 w = wr[o4];
            a0 = fmaf(w.x, f[o4*4+0], a0);
            a1 = fmaf(w.y, f[o4*4+1], a1);
            a2 = fmaf(w.z, f[o4*4+2], a2);
            a3 = fmaf(w.w, f[o4*4+3], a3);
        }
        if (t < KK)
            kp[(size_t)t * HW] = (a0 + a1) + (a2 + a3) + b2[t];
    }
}

// ---------------------------------------------------------------------------
// Kernel 2: involution with packed f32x2 (FFMA2) channel pairs.
// grid 1024 = (b, 16 4-row tiles, 16 8-channel groups), 128 threads.
// smem: xs2[chpair p][10 rows][76 positions] of float-pairs (ch 2p, 2p+1);
// position q holds global col q-4 (cols 0..3 and 68..75 are zero halo).
// Thread = (row hloc, 2 px at wloc) x 4 channel pairs.
// Per tap-row: 7 LDG.64 kv + 14 dup-packs + per pair 5 LDS.128 + 14 FFMA2.
// ---------------------------------------------------------------------------
__global__ __launch_bounds__(128, 5) void inv_kernel(
    const float* __restrict__ x, float* __restrict__ out)
{
    __shared__ __align__(16) u64t xs2[4 * 10 * 76];   // 24320 B

    const int bx = blockIdx.x;              // 0..1023
    const int b  = bx >> 8;
    const int ht = (bx >> 4) & 15;          // 16 row-tiles of 4
    const int cg = bx & 15;                 // 16 groups of 8 channels
    const int h0 = ht * 4;
    const int c0 = cg * 8;

    const int tid  = threadIdx.x;
    const int hloc = tid >> 5;              // 0..3
    const int lane = tid & 31;
    const int wloc = lane * 2;

    // ---- halo fill: tasks (p, r, k), 640 total, 5 per thread ----
    // each task: 2 LDG.128 (ch 2p, 2p+1) -> 4 packs -> 2 STS.128
    #pragma unroll
    for (int it = 0; it < 5; it++) {
        int idx = tid + it * 128;           // 0..639
        int p   = idx / 160;
        int rem = idx - p * 160;
        int r   = rem >> 4;
        int k   = rem & 15;
        int gr  = h0 - 3 + r;
        float4 va = make_float4(0.f, 0.f, 0.f, 0.f);
        float4 vb = va;
        if ((unsigned)gr < 64u) {
            const float* base = x + ((size_t)(b * NC + c0 + 2 * p) << 12)
                                  + (gr << 6) + (k << 2);
            va = *(const float4*)(base);
            vb = *(const float4*)(base + HW);   // next channel
        }
        u64t* d = xs2 + (p * 10 + r) * 76 + 4 + (k << 2);
        ((ulonglong2*)d)[0] = make_ulonglong2(pack2(va.x, vb.x), pack2(va.y, vb.y));
        ((ulonglong2*)d)[1] = make_ulonglong2(pack2(va.z, vb.z), pack2(va.w, vb.w));
    }
    // ---- edge zero: positions 0..3 and 68..75 per (p, r): 480 pairs ----
    #pragma unroll
    for (int it = 0; it < 4; it++) {
        int idx = tid + it * 128;           // 0..511
        if (idx < 480) {
            int p   = idx / 120;
            int rem = idx - p * 120;
            int r   = rem / 12;
            int e   = rem - r * 12;
            int pos = (e < 4) ? e : (64 + e);   // 0..3, 68..75
            xs2[(p * 10 + r) * 76 + pos] = 0ull;
        }
    }

    const float* kpix = g_kernel + (size_t)b * KK * HW + (h0 + hloc) * 64 + wloc;

    u64t accx[4], accy[4];
    #pragma unroll
    for (int p = 0; p < 4; p++) { accx[p] = 0ull; accy[p] = 0ull; }

    __syncthreads();

    #pragma unroll 1
    for (int i = 0; i < 7; i++) {
        // kv for this tap-row (7 x float2, L2-resident) -> dup-packed lanes
        u64t wx[7], wy[7];
        #pragma unroll
        for (int j = 0; j < 7; j++) {
            float2 k2 = *(const float2*)(kpix + (size_t)(i * 7 + j) * HW);
            wx[j] = pack2(k2.x, k2.x);
            wy[j] = pack2(k2.y, k2.y);
        }
        #pragma unroll
        for (int p = 0; p < 4; p++) {
            const u64t* rp = xs2 + (p * 10 + hloc + i) * 76 + wloc;
            ulonglong2 q0 = ((const ulonglong2*)rp)[0];
            ulonglong2 q1 = ((const ulonglong2*)rp)[1];
            ulonglong2 q2 = ((const ulonglong2*)rp)[2];
            ulonglong2 q3 = ((const ulonglong2*)rp)[3];
            ulonglong2 q4 = ((const ulonglong2*)rp)[4];
            u64t u1 = q0.y, u2 = q1.x, u3 = q1.y, u4 = q2.x, u5 = q2.y;
            u64t u6 = q3.x, u7 = q3.y, u8 = q4.x;
            u64t ax = accx[p], ay = accy[p];
            ax = ffma2(wx[0], u1, ax);  ay = ffma2(wy[0], u2, ay);
            ax = ffma2(wx[1], u2, ax);  ay = ffma2(wy[1], u3, ay);
            ax = ffma2(wx[2], u3, ax);  ay = ffma2(wy[2], u4, ay);
            ax = ffma2(wx[3], u4, ax);  ay = ffma2(wy[3], u5, ay);
            ax = ffma2(wx[4], u5, ax);  ay = ffma2(wy[4], u6, ay);
            ax = ffma2(wx[5], u6, ax);  ay = ffma2(wy[5], u7, ay);
            ax = ffma2(wx[6], u7, ax);  ay = ffma2(wy[6], u8, ay);
            accx[p] = ax; accy[p] = ay;
        }
    }

    const size_t out_pix = (size_t)(h0 + hloc) * 64 + wloc;
    #pragma unroll
    for (int p = 0; p < 4; p++) {
        float ax0, ax1, ay0, ay1;
        unpack2(accx[p], ax0, ax1);
        unpack2(accy[p], ay0, ay1);
        float* o0 = out + ((size_t)(b * NC + c0 + 2 * p) << 12) + out_pix;
        float2 r0; r0.x = ax0; r0.y = ay0;
        float2 r1; r1.x = ax1; r1.y = ay1;
        *(float2*)(o0)      = r0;
        *(float2*)(o0 + HW) = r1;
    }
}

extern "C" void kernel_launch(void* const* d_in, const int* in_sizes, int n_in,
                              void* d_out, int out_size)
{
    const float* x     = (const float*)d_in[0];
    const float* w1    = (const float*)d_in[1];
    const float* b1    = (const float*)d_in[2];
    const float* gamma = (const float*)d_in[3];
    const float* beta  = (const float*)d_in[4];
    const float* mean  = (const float*)d_in[5];
    const float* var   = (const float*)d_in[6];
    const float* w2    = (const float*)d_in[7];
    const float* b2    = (const float*)d_in[8];

    gen_kernel<<<256, 256>>>(x, w1, b1, gamma, beta, mean, var, w2, b2);
    inv_kernel<<<1024, 128>>>(x, (float*)d_out);
}

// round 12
// speedup vs baseline: 1.1460x; 1.0471x over previous
#include <cuda_runtime.h>

#define HW   4096
#define NC   128
#define CR   32
#define KK   49

// scratch for generated per-pixel kernels: [B=4][49][64*64]
__device__ float g_kernel[4 * KK * HW];

// ---------------------------------------------------------------------------
// Kernel 1: generate involution kernels (R4 proven version).
// 256 blocks x 256 threads. Block = 64 pixels, 4 "parts" per pixel.
// ---------------------------------------------------------------------------
__global__ __launch_bounds__(256, 3) void gen_kernel(
    const float* __restrict__ x,  const float* __restrict__ w1,
    const float* __restrict__ b1, const float* __restrict__ gamma,
    const float* __restrict__ beta, const float* __restrict__ mean,
    const float* __restrict__ var,  const float* __restrict__ w2,
    const float* __restrict__ b2)
{
    __shared__ __align__(16) float w1t[NC * CR];      // [c][o]  16 KB
    __shared__ __align__(16) float w2tt[52 * CR];     // [t][o]  6.5 KB
    __shared__ __align__(16) float fbuf[4 * CR * 64]; // [part][o][pix] 32 KB
    __shared__ float s_scale[CR], s_shift[CR];

    const int tid = threadIdx.x;

    for (int i = tid; i < NC * CR; i += 256) {
        int o = i >> 7, c = i & 127;
        w1t[c * CR + o] = w1[i];
    }
    for (int i = tid; i < 52 * CR; i += 256)
        w2tt[i] = (i < KK * CR) ? w2[i] : 0.f;
    if (tid < CR) {
        float sc = gamma[tid] * rsqrtf(var[tid] + 1e-5f);
        s_scale[tid] = sc;
        s_shift[tid] = fmaf(b1[tid], sc, beta[tid] - mean[tid] * sc);
    }
    __syncthreads();

    const int pix_l = tid & 63;
    const int part  = tid >> 6;            // warp-uniform
    const int pixel = blockIdx.x * 64 + pix_l;
    const int b     = pixel >> 12;
    const int hw    = pixel & (HW - 1);

    // ---- stage 1: partial 1x1 conv over this part's 32 channels ----
    float fp[CR];
    #pragma unroll
    for (int o = 0; o < CR; o++) fp[o] = 0.f;

    const float* xp = x + ((size_t)(b * NC + part * 32)) * HW + hw;
    #pragma unroll 8
    for (int c = 0; c < 32; c++) {
        float xv = xp[(size_t)c * HW];
        const float4* wr = (const float4*)&w1t[(part * 32 + c) * CR];
        #pragma unroll
        for (int o4 = 0; o4 < 8; o4++) {
            float4 w = wr[o4];
            fp[o4*4+0] = fmaf(w.x, xv, fp[o4*4+0]);
            fp[o4*4+1] = fmaf(w.y, xv, fp[o4*4+1]);
            fp[o4*4+2] = fmaf(w.z, xv, fp[o4*4+2]);
            fp[o4*4+3] = fmaf(w.w, xv, fp[o4*4+3]);
        }
    }
    {
        float* fb = fbuf + part * (CR * 64) + pix_l;
        #pragma unroll
        for (int o = 0; o < CR; o++) fb[o * 64] = fp[o];
    }
    __syncthreads();

    // ---- stage 2: combine partials + BN + ReLU ----
    float f[CR];
    #pragma unroll
    for (int o = 0; o < CR; o++) {
        float v = fbuf[0*(CR*64) + o*64 + pix_l]
                + fbuf[1*(CR*64) + o*64 + pix_l]
                + fbuf[2*(CR*64) + o*64 + pix_l]
                + fbuf[3*(CR*64) + o*64 + pix_l];
        v = fmaf(v, s_scale[o], s_shift[o]);
        f[o] = fmaxf(v, 0.f);
    }

    // ---- stage 3: this part's 13 kernel outputs ----
    const int t0 = part * 13;
    float* kp = g_kernel + (size_t)b * KK * HW + hw;
    #pragma unroll
    for (int tt = 0; tt < 13; tt++) {
        int t = t0 + tt;
        const float4* wr = (const float4*)&w2tt[t * CR];
        float a0 = 0.f, a1 = 0.f, a2 = 0.f, a3 = 0.f;
        #pragma unroll
        for (int o4 = 0; o4 < 8; o4++) {
            float4 w = wr[o4];
            a0 = fmaf(w.x, f[o4*4+0], a0);
            a1 = fmaf(w.y, f[o4*4+1], a1);
            a2 = fmaf(w.z, f[o4*4+2], a2);
            a3 = fmaf(w.w, f[o4*4+3], a3);
        }
        if (t < KK)
            kp[(size_t)t * HW] = (a0 + a1) + (a2 + a3) + b2[t];
    }
}

// ---------------------------------------------------------------------------
// Kernel 2: involution accumulation — R6 structure, 4 channels per block.
// grid 2048 = (b, 16 4-row tiles, 32 4-channel groups), 128 threads.
// Thread = (row hloc, 2 px at wloc) x 4 channels: 8 outputs/thread ->
// 8192 warps chip-wide (~2x R6 occupancy). Regs ~56 -> 9 blocks/SM.
// Halo: 5 aligned LDG.128 per thread + edge-zero pass (low MLP_p1).
// taps-outer/channels-inner, kv double-buffered, 8 FMA chains.
// ---------------------------------------------------------------------------
__global__ __launch_bounds__(128, 9) void inv_kernel(
    const float* __restrict__ x, float* __restrict__ out)
{
    __shared__ __align__(16) float xs[4 * 10 * 72];   // 11520 B

    const int bx = blockIdx.x;              // 0..2047
    const int b  = bx >> 9;
    const int ht = (bx >> 5) & 15;          // 16 row-tiles of 4
    const int cg = bx & 31;                 // 32 groups of 4 channels
    const int h0 = ht * 4;
    const int c0 = cg * 4;

    const int tid  = threadIdx.x;
    const int hloc = tid >> 5;              // 0..3
    const int lane = tid & 31;
    const int wloc = lane * 2;

    // ---- halo main fill: 640 aligned float4 loads (5 per thread) ----
    #pragma unroll
    for (int it = 0; it < 5; it++) {
        int idx = tid + it * 128;           // 0..639
        int ch  = idx / 160;
        int rem = idx - ch * 160;
        int r   = rem >> 4;
        int k   = rem & 15;
        int gr  = h0 - 3 + r;
        float4 v = make_float4(0.f, 0.f, 0.f, 0.f);
        if ((unsigned)gr < 64u)
            v = *(const float4*)(x + ((size_t)(b * NC + c0 + ch) << 12)
                                   + (gr << 6) + (k << 2));
        float* d = xs + ch * 720 + r * 72 + 3 + (k << 2);
        d[0] = v.x; d[1] = v.y; d[2] = v.z; d[3] = v.w;
    }
    // ---- halo edges: cols 0..2 and 67..71 -> zero (320 slots) ----
    #pragma unroll
    for (int it = 0; it < 3; it++) {
        int idx = tid + it * 128;           // 0..383
        if (idx < 320) {
            int ch  = idx / 80;
            int rem = idx - ch * 80;
            int r   = rem >> 3;
            int e   = rem & 7;
            int col = (e < 3) ? e : (64 + e);   // 0,1,2,67..71
            xs[ch * 720 + r * 72 + col] = 0.f;
        }
    }

    const float* kpix = g_kernel + (size_t)b * KK * HW + (h0 + hloc) * 64 + wloc;

    float ax[4], ay[4];
    #pragma unroll
    for (int cc = 0; cc < 4; cc++) { ax[cc] = 0.f; ay[cc] = 0.f; }

    // prefetch kernel row 0
    float2 kr[7], krn[7];
    #pragma unroll
    for (int j = 0; j < 7; j++)
        kr[j] = *(const float2*)(kpix + (size_t)j * HW);

    __syncthreads();

    #pragma unroll 1
    for (int i = 0; i < 7; i++) {
        if (i < 6) {
            #pragma unroll
            for (int j = 0; j < 7; j++)
                krn[j] = *(const float2*)(kpix + (size_t)((i + 1) * 7 + j) * HW);
        }
        const float* xrow = xs + (hloc + i) * 72 + wloc;
        #pragma unroll
        for (int cc = 0; cc < 4; cc++) {
            const float2* rp = (const float2*)(xrow + cc * 720);
            float2 v0 = rp[0], v1 = rp[1], v2 = rp[2], v3 = rp[3];
            float a = ax[cc], y = ay[cc];
            a = fmaf(kr[0].x, v0.x, a);  y = fmaf(kr[0].y, v0.y, y);
            a = fmaf(kr[1].x, v0.y, a);  y = fmaf(kr[1].y, v1.x, y);
            a = fmaf(kr[2].x, v1.x, a);  y = fmaf(kr[2].y, v1.y, y);
            a = fmaf(kr[3].x, v1.y, a);  y = fmaf(kr[3].y, v2.x, y);
            a = fmaf(kr[4].x, v2.x, a);  y = fmaf(kr[4].y, v2.y, y);
            a = fmaf(kr[5].x, v2.y, a);  y = fmaf(kr[5].y, v3.x, y);
            a = fmaf(kr[6].x, v3.x, a);  y = fmaf(kr[6].y, v3.y, y);
            ax[cc] = a; ay[cc] = y;
        }
        #pragma unroll
        for (int j = 0; j < 7; j++) kr[j] = krn[j];
    }

    const size_t out_pix = (size_t)(h0 + hloc) * 64 + wloc;
    #pragma unroll
    for (int cc = 0; cc < 4; cc++) {
        float2 res; res.x = ax[cc]; res.y = ay[cc];
        *(float2*)(out + ((size_t)(b * NC + c0 + cc) << 12) + out_pix) = res;
    }
}

extern "C" void kernel_launch(void* const* d_in, const int* in_sizes, int n_in,
                              void* d_out, int out_size)
{
    const float* x     = (const float*)d_in[0];
    const float* w1    = (const float*)d_in[1];
    const float* b1    = (const float*)d_in[2];
    const float* gamma = (const float*)d_in[3];
    const float* beta  = (const float*)d_in[4];
    const float* mean  = (const float*)d_in[5];
    const float* var   = (const float*)d_in[6];
    const float* w2    = (const float*)d_in[7];
    const float* b2    = (const float*)d_in[8];

    gen_kernel<<<256, 256>>>(x, w1, b1, gamma, beta, mean, var, w2, b2);
    inv_kernel<<<2048, 128>>>(x, (float*)d_out);
}

// round 14
// speedup vs baseline: 1.2743x; 1.1120x over previous
#include <cuda_runtime.h>

#define HW   4096
#define NC   128
#define CR   32
#define KK   49

// scratch for generated per-pixel kernels: [B=4][49][64*64]
__device__ float g_kernel[4 * KK * HW];

// ---------------------------------------------------------------------------
// Kernel 1: generate involution kernels (R4 proven version).
// 256 blocks x 256 threads. Block = 64 pixels, 4 "parts" per pixel.
// ---------------------------------------------------------------------------
__global__ __launch_bounds__(256, 3) void gen_kernel(
    const float* __restrict__ x,  const float* __restrict__ w1,
    const float* __restrict__ b1, const float* __restrict__ gamma,
    const float* __restrict__ beta, const float* __restrict__ mean,
    const float* __restrict__ var,  const float* __restrict__ w2,
    const float* __restrict__ b2)
{
    __shared__ __align__(16) float w1t[NC * CR];      // [c][o]  16 KB
    __shared__ __align__(16) float w2tt[52 * CR];     // [t][o]  6.5 KB
    __shared__ __align__(16) float fbuf[4 * CR * 64]; // [part][o][pix] 32 KB
    __shared__ float s_scale[CR], s_shift[CR];

    const int tid = threadIdx.x;

    for (int i = tid; i < NC * CR; i += 256) {
        int o = i >> 7, c = i & 127;
        w1t[c * CR + o] = w1[i];
    }
    for (int i = tid; i < 52 * CR; i += 256)
        w2tt[i] = (i < KK * CR) ? w2[i] : 0.f;
    if (tid < CR) {
        float sc = gamma[tid] * rsqrtf(var[tid] + 1e-5f);
        s_scale[tid] = sc;
        s_shift[tid] = fmaf(b1[tid], sc, beta[tid] - mean[tid] * sc);
    }
    __syncthreads();

    const int pix_l = tid & 63;
    const int part  = tid >> 6;            // warp-uniform
    const int pixel = blockIdx.x * 64 + pix_l;
    const int b     = pixel >> 12;
    const int hw    = pixel & (HW - 1);

    // ---- stage 1: partial 1x1 conv over this part's 32 channels ----
    float fp[CR];
    #pragma unroll
    for (int o = 0; o < CR; o++) fp[o] = 0.f;

    const float* xp = x + ((size_t)(b * NC + part * 32)) * HW + hw;
    #pragma unroll 8
    for (int c = 0; c < 32; c++) {
        float xv = xp[(size_t)c * HW];
        const float4* wr = (const float4*)&w1t[(part * 32 + c) * CR];
        #pragma unroll
        for (int o4 = 0; o4 < 8; o4++) {
            float4 w = wr[o4];
            fp[o4*4+0] = fmaf(w.x, xv, fp[o4*4+0]);
            fp[o4*4+1] = fmaf(w.y, xv, fp[o4*4+1]);
            fp[o4*4+2] = fmaf(w.z, xv, fp[o4*4+2]);
            fp[o4*4+3] = fmaf(w.w, xv, fp[o4*4+3]);
        }
    }
    {
        float* fb = fbuf + part * (CR * 64) + pix_l;
        #pragma unroll
        for (int o = 0; o < CR; o++) fb[o * 64] = fp[o];
    }
    __syncthreads();

    // ---- stage 2: combine partials + BN + ReLU ----
    float f[CR];
    #pragma unroll
    for (int o = 0; o < CR; o++) {
        float v = fbuf[0*(CR*64) + o*64 + pix_l]
                + fbuf[1*(CR*64) + o*64 + pix_l]
                + fbuf[2*(CR*64) + o*64 + pix_l]
                + fbuf[3*(CR*64) + o*64 + pix_l];
        v = fmaf(v, s_scale[o], s_shift[o]);
        f[o] = fmaxf(v, 0.f);
    }

    // ---- stage 3: this part's 13 kernel outputs ----
    const int t0 = part * 13;
    float* kp = g_kernel + (size_t)b * KK * HW + hw;
    #pragma unroll
    for (int tt = 0; tt < 13; tt++) {
        int t = t0 + tt;
        const float4* wr = (const float4*)&w2tt[t * CR];
        float a0 = 0.f, a1 = 0.f, a2 = 0.f, a3 = 0.f;
        #pragma unroll
        for (int o4 = 0; o4 < 8; o4++) {
            float4 w = wr[o4];
            a0 = fmaf(w.x, f[o4*4+0], a0);
            a1 = fmaf(w.y, f[o4*4+1], a1);
            a2 = fmaf(w.z, f[o4*4+2], a2);
            a3 = fmaf(w.w, f[o4*4+3], a3);
        }
        if (t < KK)
            kp[(size_t)t * HW] = (a0 + a1) + (a2 + a3) + b2[t];
    }
}

// ---------------------------------------------------------------------------
// Kernel 2: involution, 4 px/thread + 8 ch/thread, kv double-buffered.
// grid 512 = (b, 8 8-row tiles, 16 8-channel groups), 128 threads -> one
// full wave at 4 blocks/SM. Thread = (row = tid>>4, 4 px at (tid&15)*4).
// Per tap-row: 7 LDG.128 kv (prefetched one row ahead), per channel
// 2 LDS.128 + 1 LDS.64 feed 32 independent FMA chains.
// Traffic/output ~= 70B x-smem + 24.5B kv (0.69x of R6).
// ---------------------------------------------------------------------------
__global__ __launch_bounds__(128, 4) void inv_kernel(
    const float* __restrict__ x, float* __restrict__ out)
{
    __shared__ __align__(16) float xs[8 * 14 * 72];   // 32256 B

    const int bx = blockIdx.x;              // 0..511
    const int b  = bx >> 7;
    const int ht = (bx >> 4) & 7;           // 8 row-tiles of 8
    const int cg = bx & 15;                 // 16 groups of 8 channels
    const int h0 = ht * 8;
    const int c0 = cg * 8;

    const int tid  = threadIdx.x;
    const int row  = tid >> 4;              // 0..7 output row
    const int wloc = (tid & 15) * 4;        // 0,4,...,60

    // ---- halo main fill: 1792 aligned float4 loads (14 per thread) ----
    #pragma unroll
    for (int it = 0; it < 14; it++) {
        int idx = tid + it * 128;           // 0..1791
        int ch  = idx / 224;                // 14*16 per channel
        int rem = idx - ch * 224;
        int r   = rem >> 4;
        int k   = rem & 15;
        int gr  = h0 - 3 + r;
        float4 v = make_float4(0.f, 0.f, 0.f, 0.f);
        if ((unsigned)gr < 64u)
            v = *(const float4*)(x + ((size_t)(b * NC + c0 + ch) << 12)
                                   + (gr << 6) + (k << 2));
        float* d = xs + ch * 1008 + r * 72 + 3 + (k << 2);
        d[0] = v.x; d[1] = v.y; d[2] = v.z; d[3] = v.w;
    }
    // ---- halo edges: cols 0..2 and 67..71 -> zero (7 per thread) ----
    #pragma unroll
    for (int it = 0; it < 7; it++) {
        int idx = tid + it * 128;           // 0..895
        int ch  = idx / 112;                // 14*8 per channel
        int rem = idx - ch * 112;
        int r   = rem >> 3;
        int e   = rem & 7;
        int col = (e < 3) ? e : (64 + e);   // 0,1,2,67..71
        xs[ch * 1008 + r * 72 + col] = 0.f;
    }

    const float* kpix = g_kernel + (size_t)b * KK * HW + (h0 + row) * 64 + wloc;

    float acc[8][4];
    #pragma unroll
    for (int cc = 0; cc < 8; cc++)
        #pragma unroll
        for (int p = 0; p < 4; p++) acc[cc][p] = 0.f;

    // prefetch kernel tap-row 0 (overlaps halo STS drain)
    float4 kr[7], krn[7];
    #pragma unroll
    for (int j = 0; j < 7; j++)
        kr[j] = *(const float4*)(kpix + (size_t)j * HW);

    __syncthreads();

    #pragma unroll 1
    for (int i = 0; i < 7; i++) {
        // prefetch next tap-row's weights while computing this one
        if (i < 6) {
            #pragma unroll
            for (int j = 0; j < 7; j++)
                krn[j] = *(const float4*)(kpix + (size_t)((i + 1) * 7 + j) * HW);
        }
        const float* xrow = xs + (row + i) * 72 + wloc;
        #pragma unroll
        for (int cc = 0; cc < 8; cc++) {
            const float* rp = xrow + cc * 1008;
            float4 u0 = *(const float4*)(rp);
            float4 u1 = *(const float4*)(rp + 4);
            float2 u2 = *(const float2*)(rp + 8);
            float va[10] = {u0.x,u0.y,u0.z,u0.w, u1.x,u1.y,u1.z,u1.w, u2.x,u2.y};
            float a0 = acc[cc][0], a1 = acc[cc][1], a2 = acc[cc][2], a3 = acc[cc][3];
            #pragma unroll
            for (int j = 0; j < 7; j++) {
                a0 = fmaf(kr[j].x, va[j],     a0);
                a1 = fmaf(kr[j].y, va[j + 1], a1);
                a2 = fmaf(kr[j].z, va[j + 2], a2);
                a3 = fmaf(kr[j].w, va[j + 3], a3);
            }
            acc[cc][0] = a0; acc[cc][1] = a1; acc[cc][2] = a2; acc[cc][3] = a3;
        }
        #pragma unroll
        for (int j = 0; j < 7; j++) kr[j] = krn[j];
    }

    const size_t out_pix = (size_t)(h0 + row) * 64 + wloc;
    #pragma unroll
    for (int cc = 0; cc < 8; cc++) {
        float4 res;
        res.x = acc[cc][0]; res.y = acc[cc][1];
        res.z = acc[cc][2]; res.w = acc[cc][3];
        *(float4*)(out + ((size_t)(b * NC + c0 + cc) << 12) + out_pix) = res;
    }
}

extern "C" void kernel_launch(void* const* d_in, const int* in_sizes, int n_in,
                              void* d_out, int out_size)
{
    const float* x     = (const float*)d_in[0];
    const float* w1    = (const float*)d_in[1];
    const float* b1    = (const float*)d_in[2];
    const float* gamma = (const float*)d_in[3];
    const float* beta  = (const float*)d_in[4];
    const float* mean  = (const float*)d_in[5];
    const float* var   = (const float*)d_in[6];
    const float* w2    = (const float*)d_in[7];
    const float* b2    = (const float*)d_in[8];

    gen_kernel<<<256, 256>>>(x, w1, b1, gamma, beta, mean, var, w2, b2);
    inv_kernel<<<512, 128>>>(x, (float*)d_out);
}